// round 8
// baseline (speedup 1.0000x reference)
#include <cuda_runtime.h>

#define NPTS 2048
#define KCAP 256
#define NTHREADS 256
#define WARPS_PER_ROW 8
#define STAGE_CAP 256   // provably sufficient: idx>=256 => off>=KCAP => dropped anyway
#define CUT2 0.09f

// d_out layout (float32):
//   [0, N*K)            neighbours (N,K)
//   [N*K, N*K*4)        cell_indices (N,K,3)
//   [N*K*4]             actual_max
#define MAX_OFFSET ((size_t)NPTS * KCAP * 4)

// Scratch (allocation-free __device__ globals)
__device__ float4 g_p4[NPTS];          // packed positions
__device__ int    g_list[27 * NPTS];   // per-cell eligible j, ascending
__device__ int    g_cnt[27];

__global__ void pb_pack_kernel(const float* __restrict__ pos, float* __restrict__ out_max) {
    const int j = blockIdx.x * blockDim.x + threadIdx.x;
    if (j < NPTS) {
        g_p4[j] = make_float4(pos[3 * j], pos[3 * j + 1], pos[3 * j + 2], 0.0f);
    }
    if (j == 0) *out_max = 0.0f;
}

// One warp per cell: build j-ascending candidate list from per-dim bands on j.
//  shift -1 on dim d  =>  p_j.d >= p_i.d + 0.7 >= 0.7      (margin: > 0.69990)
//  shift +1 on dim d  =>  p_j.d <= p_i.d - 0.7 <  0.3      (margin: < 0.30010)
__global__ void pb_lists_kernel() {
    const int c    = blockIdx.x;
    const int lane = threadIdx.x;
    const unsigned lmask = (1u << lane) - 1u;
    const int sx = (c % 3) - 1, sy = ((c / 3) % 3) - 1, sz = (c / 9) - 1;
    if (c == 13) { if (lane == 0) g_cnt[13] = NPTS; return; }  // self cell: full scan

    int* __restrict__ lst = &g_list[c * NPTS];
    int cnt = 0;
    for (int chunk = 0; chunk < NPTS; chunk += 32) {
        const int j = chunk + lane;
        const float4 p = g_p4[j];
        bool ok = true;
        if (sx < 0) ok &= (p.x > 0.69990f);
        if (sx > 0) ok &= (p.x < 0.30010f);
        if (sy < 0) ok &= (p.y > 0.69990f);
        if (sy > 0) ok &= (p.y < 0.30010f);
        if (sz < 0) ok &= (p.z > 0.69990f);
        if (sz > 0) ok &= (p.z < 0.30010f);
        const unsigned b = __ballot_sync(0xFFFFFFFFu, ok);
        if (ok) lst[cnt + __popc(b & lmask)] = j;
        cnt += __popc(b);
    }
    if (lane == 0) g_cnt[c] = cnt;
}

__global__ __launch_bounds__(NTHREADS)
void pb_nbr_kernel(float* __restrict__ out) {
    __shared__ int stage[WARPS_PER_ROW][STAGE_CAP];   // 8 KB
    __shared__ int scount[WARPS_PER_ROW];

    const int tid  = threadIdx.x;
    const int lane = tid & 31;
    const int q    = tid >> 5;
    const unsigned lmask = (1u << lane) - 1u;

    const int i = blockIdx.x;                  // one row per block
    const float4 pc = __ldg(&g_p4[i]);
    const float pix = pc.x, piy = pc.y, piz = pc.z;

    // Centre-side feasibility (margin 1e-4 >> fp32 rounding).
    const bool okx[3] = { pix < 0.30001f, true, pix > 0.69999f };
    const bool oky[3] = { piy < 0.30001f, true, piy > 0.69999f };
    const bool okz[3] = { piz < 0.30001f, true, piz > 0.69999f };

    // Total ordered chunk count over active cells (self = 64 chunks).
    int T = 0;
#pragma unroll
    for (int c = 0; c < 27; c++) {
        const int sx = (c % 3) - 1, sy = ((c / 3) % 3) - 1, sz = (c / 9) - 1;
        if (okx[sx + 1] && oky[sy + 1] && okz[sz + 1]) {
            T += (c == 13) ? (NPTS / 32) : ((__ldg(&g_cnt[c]) + 31) >> 5);
        }
    }
    const int span = (T + WARPS_PER_ROW - 1) / WARPS_PER_ROW;
    const int t0 = q * span;
    const int t1 = (t0 + span < T) ? (t0 + span) : T;

    int* __restrict__ mystage = stage[q];
    int scnt = 0;              // uniform in warp
    int tbase = 0;

    for (int c = 0; c < 27; c++) {
        const int sx = (c % 3) - 1, sy = ((c / 3) % 3) - 1, sz = (c / 9) - 1;
        if (!(okx[sx + 1] && oky[sy + 1] && okz[sz + 1])) continue;

        const bool selfc = (c == 13);
        const int cnt_c  = selfc ? NPTS : __ldg(&g_cnt[c]);
        const int nc     = (cnt_c + 31) >> 5;
        const int lo = (t0 > tbase) ? t0 : tbase;
        const int hi = (t1 < tbase + nc) ? t1 : tbase + nc;

        if (lo < hi) {
            const float fsx = (float)sx, fsy = (float)sy, fsz = (float)sz;
            const int* __restrict__ lst = &g_list[c * NPTS];
            for (int t = lo; t < hi; t++) {
                const int idx = ((t - tbase) << 5) + lane;
                bool valid; int j;
                if (selfc) { valid = true; j = idx; }
                else       { valid = (idx < cnt_c); j = valid ? __ldg(&lst[idx]) : 0; }
                const float4 p = __ldg(&g_p4[j]);
                // Exact reference rounding: ((p_j + s) - p_i), plain mul/add, no FMA.
                const float dx = __fadd_rn(__fadd_rn(p.x, fsx), -pix);
                const float dy = __fadd_rn(__fadd_rn(p.y, fsy), -piy);
                const float dz = __fadd_rn(__fadd_rn(p.z, fsz), -piz);
                const float d2 = __fadd_rn(__fadd_rn(__fmul_rn(dx, dx), __fmul_rn(dy, dy)),
                                           __fmul_rn(dz, dz));
                const bool hit = valid && (d2 <= CUT2) && !(selfc && (j == i));

                const unsigned b = __ballot_sync(0xFFFFFFFFu, hit);
                if (b) {
                    if (hit) {
                        const int sidx = scnt + __popc(b & lmask);
                        if (sidx < STAGE_CAP) mystage[sidx] = (c << 11) | j;
                    }
                    scnt += __popc(b);
                }
            }
        }
        tbase += nc;
    }

    if (lane == 0) scount[q] = scnt;
    __syncthreads();

    int base = 0, rowTotal = 0;
#pragma unroll
    for (int q2 = 0; q2 < WARPS_PER_ROW; q2++) {
        const int cc = scount[q2];
        if (q2 < q) base += cc;
        rowTotal += cc;
    }

    float* __restrict__ out_neigh = out + (size_t)i * KCAP;
    float* __restrict__ out_cells = out + (size_t)NPTS * KCAP + (size_t)i * KCAP * 3;

    // Copy this warp's in-order staged segment to its prefix position.
    const int nwrite = (scnt < STAGE_CAP) ? scnt : STAGE_CAP;
    for (int e = lane; e < nwrite; e += 32) {
        const int off = base + e;
        if (off < KCAP) {
            const int code = mystage[e];
            const int j = code & 2047;
            const int c = code >> 11;
            out_neigh[off]         = (float)j;
            out_cells[3 * off]     = (float)((c % 3) - 1);
            out_cells[3 * off + 1] = (float)(((c / 3) % 3) - 1);
            out_cells[3 * off + 2] = (float)((c / 9) - 1);
        }
    }

    // Tail fill: neighbours=-1, cells=(1,1,1) (jnp.take wraps -1 -> last row)
    const int filled = (rowTotal < KCAP) ? rowTotal : KCAP;
    for (int k = filled + tid; k < KCAP; k += NTHREADS) {
        out_neigh[k]         = -1.0f;
        out_cells[3 * k]     = 1.0f;
        out_cells[3 * k + 1] = 1.0f;
        out_cells[3 * k + 2] = 1.0f;
    }
    if (tid == 0) {
        atomicMax((int*)(out + MAX_OFFSET), __float_as_int((float)rowTotal));
    }
}

extern "C" void kernel_launch(void* const* d_in, const int* in_sizes, int n_in,
                              void* d_out, int out_size) {
    const float* pos = (const float*)d_in[0];
    float* out = (float*)d_out;
    pb_pack_kernel<<<(NPTS + 255) / 256, 256>>>(pos, out + MAX_OFFSET);
    pb_lists_kernel<<<27, 32>>>();
    pb_nbr_kernel<<<NPTS, NTHREADS>>>(out);
}

// round 9
// speedup vs baseline: 1.1850x; 1.1850x over previous
#include <cuda_runtime.h>

#define NPTS 2048
#define KCAP 256
#define NTHREADS 512
#define ROWS_PER_BLOCK 4
#define WARPS_PER_ROW 4
#define NWARPS (ROWS_PER_BLOCK * WARPS_PER_ROW)
#define STAGE_CAP 256   // provably sufficient: idx>=256 => off>=KCAP => dropped anyway
#define CUT2 0.09f

// d_out layout (float32):
//   [0, N*K)            neighbours (N,K)
//   [N*K, N*K*4)        cell_indices (N,K,3)
//   [N*K*4]             actual_max
#define MAX_OFFSET ((size_t)NPTS * KCAP * 4)

__global__ void pb_init_kernel(float* __restrict__ out_max) {
    *out_max = 0.0f;
}

__global__ __launch_bounds__(NTHREADS, 4)
void pb_nbr_kernel(const float* __restrict__ pos, float* __restrict__ out) {
    __shared__ float4 spos[NPTS];                        // 32 KB
    __shared__ unsigned short stage[NWARPS][STAGE_CAP];  // 8 KB
    __shared__ int scount[NWARPS];

    const int tid  = threadIdx.x;
    const int lane = tid & 31;
    const int w    = tid >> 5;          // 0..15
    const int r    = w >> 2;            // row within block (0..3)
    const int q    = w & 3;             // quarter of that row's ordered work
    const unsigned lmask = (1u << lane) - 1u;

    // Cooperative fill of position cache (coalesced scalar reads, float4 STS)
    for (int j = tid; j < NPTS; j += NTHREADS) {
        spos[j] = make_float4(pos[3 * j], pos[3 * j + 1], pos[3 * j + 2], 0.0f);
    }
    __syncthreads();

    const int i = blockIdx.x * ROWS_PER_BLOCK + r;
    const float pix = spos[i].x;
    const float piy = spos[i].y;
    const float piz = spos[i].z;
    const int selfcode = (13 << 11) | i;   // uniform self-pair exclusion

    // Per-dimension shift feasibility (margin 1e-4 >> fp32 rounding).
    const bool okx[3] = { pix < 0.30001f, true, pix > 0.69999f };
    const bool oky[3] = { piy < 0.30001f, true, piy > 0.69999f };
    const bool okz[3] = { piz < 0.30001f, true, piz > 0.69999f };

    // Active-cell count: T = nA*64 ordered chunks; each warp takes exactly nA*16.
    int nA = 0;
#pragma unroll
    for (int c = 0; c < 27; c++) {
        const int sx = (c % 3) - 1, sy = ((c / 3) % 3) - 1, sz = (c / 9) - 1;
        if (okx[sx + 1] && oky[sy + 1] && okz[sz + 1]) nA++;
    }
    const int per = nA * (64 / WARPS_PER_ROW);
    const int t0 = q * per;
    const int t1 = t0 + per;

    unsigned short* __restrict__ mystage = stage[w];
    int scnt = 0;                  // uniform in warp
    int tbase = 0;

    for (int c = 0; c < 27; c++) {
        const int sx = (c % 3) - 1, sy = ((c / 3) % 3) - 1, sz = (c / 9) - 1;
        if (!(okx[sx + 1] && oky[sy + 1] && okz[sz + 1])) continue;

        const int lo = (t0 > tbase) ? t0 : tbase;
        const int hi = (t1 < tbase + 64) ? t1 : tbase + 64;
        if (lo < hi) {
            const float fsx = (float)sx, fsy = (float)sy, fsz = (float)sz;
            int code = (c << 11) | (((lo - tbase) << 5) + lane);
            for (int t = lo; t < hi; t++, code += 32) {
                const int j = code & 2047;
                const float4 p = spos[j];
                // Exact reference rounding: ((p_j + s) - p_i), plain mul/add, no FMA.
                const float dx = __fadd_rn(__fadd_rn(p.x, fsx), -pix);
                const float dy = __fadd_rn(__fadd_rn(p.y, fsy), -piy);
                const float dz = __fadd_rn(__fadd_rn(p.z, fsz), -piz);
                const float d2 = __fadd_rn(__fadd_rn(__fmul_rn(dx, dx), __fmul_rn(dy, dy)),
                                           __fmul_rn(dz, dz));
                const bool hit = (d2 <= CUT2) && (code != selfcode);

                const unsigned b = __ballot_sync(0xFFFFFFFFu, hit);
                const int idx = scnt + __popc(b & lmask);
                scnt += __popc(b);
                if (hit && idx < STAGE_CAP) mystage[idx] = (unsigned short)code;
            }
        }
        tbase += 64;
    }

    if (lane == 0) scount[w] = scnt;
    __syncthreads();

    int base = 0, rowTotal = 0;
#pragma unroll
    for (int q2 = 0; q2 < WARPS_PER_ROW; q2++) {
        const int cc = scount[(r << 2) + q2];
        if (q2 < q) base += cc;
        rowTotal += cc;
    }

    float* __restrict__ out_neigh = out + (size_t)i * KCAP;
    float* __restrict__ out_cells = out + (size_t)NPTS * KCAP + (size_t)i * KCAP * 3;

    // Copy this warp's in-order staged segment to its prefix position.
    const int nwrite = (scnt < STAGE_CAP) ? scnt : STAGE_CAP;
    for (int e = lane; e < nwrite; e += 32) {
        const int off = base + e;
        if (off < KCAP) {
            const int code = mystage[e];
            const int j = code & 2047;
            const int c = code >> 11;
            out_neigh[off]         = (float)j;
            out_cells[3 * off]     = (float)((c % 3) - 1);
            out_cells[3 * off + 1] = (float)(((c / 3) % 3) - 1);
            out_cells[3 * off + 2] = (float)((c / 9) - 1);
        }
    }

    // Tail fill by the row's 128 threads: neighbours=-1, cells=(1,1,1)
    const int rowTid = tid & 127;
    const int filled = (rowTotal < KCAP) ? rowTotal : KCAP;
    for (int k = filled + rowTid; k < KCAP; k += 128) {
        out_neigh[k]         = -1.0f;
        out_cells[3 * k]     = 1.0f;
        out_cells[3 * k + 1] = 1.0f;
        out_cells[3 * k + 2] = 1.0f;
    }
    if (q == 0 && lane == 0) {
        atomicMax((int*)(out + MAX_OFFSET), __float_as_int((float)rowTotal));
    }
}

extern "C" void kernel_launch(void* const* d_in, const int* in_sizes, int n_in,
                              void* d_out, int out_size) {
    const float* pos = (const float*)d_in[0];
    float* out = (float*)d_out;
    pb_init_kernel<<<1, 1>>>(out + MAX_OFFSET);
    pb_nbr_kernel<<<NPTS / ROWS_PER_BLOCK, NTHREADS>>>(pos, out);
}

// round 10
// speedup vs baseline: 2.5429x; 2.1460x over previous
#include <cuda_runtime.h>

#define NPTS 2048
#define KCAP 256
#define NTHREADS 256
#define ROWS_PER_BLOCK 2
#define WARPS_PER_ROW 4
#define CUT2 0.09f
#define EPSB 1e-3f
#define NWORDS 1728   // 27 cells * 64 words of 32 bits = 2048 j-bits per cell

#define MAX_OFFSET ((size_t)NPTS * KCAP * 4)

// Scratch (__device__ globals, allocation-free)
__device__ float4 g_sorted[NPTS];   // x-bucket-sorted points; .w = original j (bits)
__device__ int    g_bstart[257];    // bucket start offsets

// Single-block counting sort by x-bucket (256 buckets). Within-bucket order is
// arbitrary (atomics) — harmless: the bitmask emission canonicalizes ordering.
__global__ __launch_bounds__(256)
void pb_sort_kernel(const float* __restrict__ pos, float* __restrict__ out_max) {
    __shared__ int hist[256];
    __shared__ int cursor[256];
    __shared__ int wsum[8];
    const int tid = threadIdx.x;
    const int lane = tid & 31, w = tid >> 5;
    hist[tid] = 0;
    __syncthreads();

    float4 p[8]; int b[8];
#pragma unroll
    for (int rr = 0; rr < 8; rr++) {
        const int j = tid + rr * 256;
        const float xx = pos[3 * j], yy = pos[3 * j + 1], zz = pos[3 * j + 2];
        int bb = (int)(xx * 256.0f);
        bb = bb < 0 ? 0 : (bb > 255 ? 255 : bb);
        p[rr] = make_float4(xx, yy, zz, __int_as_float(j));
        b[rr] = bb;
        atomicAdd(&hist[bb], 1);
    }
    __syncthreads();

    // exclusive prefix over 256
    const int v = hist[tid];
    int incl = v;
#pragma unroll
    for (int d = 1; d < 32; d <<= 1) {
        const int t = __shfl_up_sync(0xFFFFFFFFu, incl, d);
        if (lane >= d) incl += t;
    }
    if (lane == 31) wsum[w] = incl;
    __syncthreads();
    int woff = 0;
    for (int k = 0; k < w; k++) woff += wsum[k];
    const int excl = woff + incl - v;
    cursor[tid] = excl;
    g_bstart[tid] = excl;
    if (tid == 0) { g_bstart[256] = NPTS; *out_max = 0.0f; }
    __syncthreads();

#pragma unroll
    for (int rr = 0; rr < 8; rr++) {
        const int dst = atomicAdd(&cursor[b[rr]], 1);
        g_sorted[dst] = p[rr];
    }
}

__global__ __launch_bounds__(NTHREADS)
void pb_nbr_kernel(const float* __restrict__ pos, float* __restrict__ out) {
    __shared__ unsigned s_mask[ROWS_PER_BLOCK][NWORDS];   // 13.5 KB
    __shared__ int s_wcnt[ROWS_PER_BLOCK][WARPS_PER_ROW];

    const int tid  = threadIdx.x;
    const int lane = tid & 31;
    const int w    = tid >> 5;
    const int r    = w >> 2;          // row within block
    const int q    = w & 3;           // warp within row

    unsigned* mz = &s_mask[0][0];
    for (int k = tid; k < ROWS_PER_BLOCK * NWORDS; k += NTHREADS) mz[k] = 0u;
    __syncthreads();

    const int i = blockIdx.x * ROWS_PER_BLOCK + r;
    const float pix = __ldg(&pos[3 * i]);
    const float piy = __ldg(&pos[3 * i + 1]);
    const float piz = __ldg(&pos[3 * i + 2]);

    // Per-dim shift feasibility (margin 1e-4 >> fp32 rounding)
    const bool okxm = pix < 0.30001f, okxp = pix > 0.69999f;
    const bool okym = piy < 0.30001f, okyp = piy > 0.69999f;
    const bool okzm = piz < 0.30001f, okzp = piz > 0.69999f;

    // (sy,sz) combo slots (per-dim at most one nonzero shift is feasible)
    const bool hy = okym || okyp;
    const bool hz = okzm || okzp;
    const float fy = okym ? -1.0f : 1.0f;
    const float fz = okzm ? -1.0f : 1.0f;
    const int iy = okym ? 0 : 2;      // (sy+1) of the shifted slot
    const int iz = okzm ? 0 : 2;

    // x segments (bucket ranges, conservative superset via EPSB margin)
    int blo0 = (int)floorf((pix - 0.3f - EPSB) * 256.0f); if (blo0 < 0) blo0 = 0;
    int bhi0 = (int)floorf((pix + 0.3f + EPSB) * 256.0f); if (bhi0 > 255) bhi0 = 255;
    int blo1 = (int)floorf((pix + 0.7f - EPSB) * 256.0f); if (blo1 > 255) blo1 = 255;
    if (blo1 < 0) blo1 = 0;
    int bhi2 = (int)floorf((pix - 0.7f + EPSB) * 256.0f); if (bhi2 > 255) bhi2 = 255;
    if (bhi2 < 0) bhi2 = 0;

    unsigned* __restrict__ rmask = s_mask[r];

    // ---- Discovery: order-free, ballot-free; hits -> bitmask atomicOr ----
#pragma unroll
    for (int s = 0; s < 3; s++) {
        bool sval; float fsx; int cadd, kb0, kb1;
        if (s == 0)      { sval = true; fsx =  0.0f; cadd = 1; kb0 = blo0; kb1 = bhi0; }
        else if (s == 1) { sval = okxm; fsx = -1.0f; cadd = 0; kb0 = blo1; kb1 = 255;  }
        else             { sval = okxp; fsx =  1.0f; cadd = 2; kb0 = 0;    kb1 = bhi2; }
        if (!sval) continue;
        const int k0 = __ldg(&g_bstart[kb0]);
        const int k1 = __ldg(&g_bstart[kb1 + 1]);

        for (int base = k0 + q * 32; base < k1; base += WARPS_PER_ROW * 32) {
            const int k = base + lane;
            const bool val = (k < k1);
            const float4 p = __ldg(&g_sorted[val ? k : k0]);
            const int jorig = __float_as_int(p.w);
            // Exact reference rounding: ((p_j + s) - p_i), plain mul/add, no FMA.
            // (+0.0f add is bit-exact and skipped where the shift is zero.)
            const float dx  = __fadd_rn(__fadd_rn(p.x, fsx), -pix);
            const float dx2 = __fmul_rn(dx, dx);
            const float dy0 = __fadd_rn(p.y, -piy);
            const float dz0 = __fadd_rn(p.z, -piz);
            const float dy0s = __fmul_rn(dy0, dy0);
            const float dz0s = __fmul_rn(dz0, dz0);
            {   // combo (0,0): c = 12 + cadd (self cell iff cadd==1)
                const float d2 = __fadd_rn(__fadd_rn(dx2, dy0s), dz0s);
                const bool hit = val && (d2 <= CUT2) && !(cadd == 1 && jorig == i);
                if (hit) atomicOr(&rmask[((12 + cadd) << 6) + (jorig >> 5)],
                                  1u << (jorig & 31));
            }
            if (hy) {
                const float dy1 = __fadd_rn(__fadd_rn(p.y, fy), -piy);
                const float dy1s = __fmul_rn(dy1, dy1);
                {
                    const float d2 = __fadd_rn(__fadd_rn(dx2, dy1s), dz0s);
                    if (val && d2 <= CUT2)
                        atomicOr(&rmask[((9 + iy * 3 + cadd) << 6) + (jorig >> 5)],
                                 1u << (jorig & 31));
                }
                if (hz) {
                    const float dz1 = __fadd_rn(__fadd_rn(p.z, fz), -piz);
                    const float dz1s = __fmul_rn(dz1, dz1);
                    const float d2 = __fadd_rn(__fadd_rn(dx2, dy1s), dz1s);
                    if (val && d2 <= CUT2)
                        atomicOr(&rmask[((iz * 9 + iy * 3 + cadd) << 6) + (jorig >> 5)],
                                 1u << (jorig & 31));
                }
            }
            if (hz) {
                const float dz1 = __fadd_rn(__fadd_rn(p.z, fz), -piz);
                const float dz1s = __fmul_rn(dz1, dz1);
                const float d2 = __fadd_rn(__fadd_rn(dx2, dy0s), dz1s);
                if (val && d2 <= CUT2)
                    atomicOr(&rmask[((iz * 9 + 3 + cadd) << 6) + (jorig >> 5)],
                             1u << (jorig & 31));
            }
        }
    }
    __syncthreads();

    // ---- Count phase: warp q counts bits in its span of the active-cell word seq ----
    const int nA = (1 + okxm + okxp) * (1 + okym + okyp) * (1 + okzm + okzp);
    const int myt0 = q * nA * 16;
    const int myt1 = myt0 + nA * 16;

    int cnt = 0;
    {
        int tb = 0;
        for (int zi = 0; zi < 3; zi++) {
            if ((zi == 0 && !okzm) || (zi == 2 && !okzp)) continue;
            for (int yi = 0; yi < 3; yi++) {
                if ((yi == 0 && !okym) || (yi == 2 && !okyp)) continue;
                for (int xi = 0; xi < 3; xi++) {
                    if ((xi == 0 && !okxm) || (xi == 2 && !okxp)) continue;
                    const int c = zi * 9 + yi * 3 + xi;
                    const int lo = myt0 > tb ? myt0 : tb;
                    const int hi = myt1 < tb + 64 ? myt1 : tb + 64;
                    for (int t = lo + lane; t < hi; t += 32)
                        cnt += __popc(rmask[(c << 6) + (t - tb)]);
                    tb += 64;
                }
            }
        }
    }
#pragma unroll
    for (int d = 16; d; d >>= 1) cnt += __shfl_xor_sync(0xFFFFFFFFu, cnt, d);
    if (lane == 0) s_wcnt[r][q] = cnt;
    __syncthreads();

    int base = 0, rowTotal = 0;
#pragma unroll
    for (int q2 = 0; q2 < WARPS_PER_ROW; q2++) {
        const int cc = s_wcnt[r][q2];
        if (q2 < q) base += cc;
        rowTotal += cc;
    }

    float* __restrict__ out_neigh = out + (size_t)i * KCAP;
    float* __restrict__ out_cells = out + (size_t)NPTS * KCAP + (size_t)i * KCAP * 3;

    // ---- Emit phase: same traversal, ordered bit expansion ----
    {
        int off = base;
        int tb = 0;
        for (int zi = 0; zi < 3; zi++) {
            if ((zi == 0 && !okzm) || (zi == 2 && !okzp)) continue;
            for (int yi = 0; yi < 3; yi++) {
                if ((yi == 0 && !okym) || (yi == 2 && !okyp)) continue;
                for (int xi = 0; xi < 3; xi++) {
                    if ((xi == 0 && !okxm) || (xi == 2 && !okxp)) continue;
                    const int c = zi * 9 + yi * 3 + xi;
                    const float fsx = (float)(xi - 1);
                    const float fsy = (float)(yi - 1);
                    const float fsz = (float)(zi - 1);
                    const int lo = myt0 > tb ? myt0 : tb;
                    const int hi = myt1 < tb + 64 ? myt1 : tb + 64;
                    for (int tg = lo; tg < hi; tg += 32) {
                        const int t = tg + lane;
                        unsigned word = (t < hi) ? rmask[(c << 6) + (t - tb)] : 0u;
                        const int pc = __popc(word);
                        int ex = pc;
#pragma unroll
                        for (int d = 1; d < 32; d <<= 1) {
                            const int tt = __shfl_up_sync(0xFFFFFFFFu, ex, d);
                            if (lane >= d) ex += tt;
                        }
                        int myoff = off + ex - pc;
                        const int jbase = (t - tb) << 5;
                        while (word) {
                            const int bit = __ffs(word) - 1;
                            word &= word - 1;
                            if (myoff < KCAP) {
                                const int j = jbase + bit;
                                out_neigh[myoff]         = (float)j;
                                out_cells[3 * myoff]     = fsx;
                                out_cells[3 * myoff + 1] = fsy;
                                out_cells[3 * myoff + 2] = fsz;
                            }
                            myoff++;
                        }
                        off += __shfl_sync(0xFFFFFFFFu, ex, 31);
                    }
                    tb += 64;
                }
            }
        }
    }

    // Tail fill by the row's 128 threads: neighbours=-1, cells=(1,1,1)
    const int rowTid = tid & 127;
    const int filled = (rowTotal < KCAP) ? rowTotal : KCAP;
    for (int k = filled + rowTid; k < KCAP; k += 128) {
        out_neigh[k]         = -1.0f;
        out_cells[3 * k]     = 1.0f;
        out_cells[3 * k + 1] = 1.0f;
        out_cells[3 * k + 2] = 1.0f;
    }
    if (q == 0 && lane == 0) {
        atomicMax((int*)(out + MAX_OFFSET), __float_as_int((float)rowTotal));
    }
}

extern "C" void kernel_launch(void* const* d_in, const int* in_sizes, int n_in,
                              void* d_out, int out_size) {
    const float* pos = (const float*)d_in[0];
    float* out = (float*)d_out;
    pb_sort_kernel<<<1, 256>>>(pos, out + MAX_OFFSET);
    pb_nbr_kernel<<<NPTS / ROWS_PER_BLOCK, NTHREADS>>>(pos, out);
}

// round 11
// speedup vs baseline: 2.8130x; 1.1062x over previous
#include <cuda_runtime.h>

#define NPTS 2048
#define KCAP 256
#define NTHREADS 256
#define ROWS_PER_BLOCK 2
#define WARPS_PER_ROW 4
#define CUT2 0.09f
#define EPSB 1e-3f
#define MWORDS 512    // 8 active-slot cells max * 64 words

#define MAX_OFFSET ((size_t)NPTS * KCAP * 4)

// Scratch (__device__ globals, allocation-free)
__device__ float4 g_sorted[NPTS];   // x-bucket-sorted points; .w = original j (bits)
__device__ int    g_bstart[257];    // bucket start offsets

// Single-block counting sort by x-bucket, 1024 threads (2 pts each).
__global__ __launch_bounds__(1024)
void pb_sort_kernel(const float* __restrict__ pos, float* __restrict__ out_max) {
    __shared__ int hist[256];
    __shared__ int cursor[256];
    __shared__ int wsum[8];
    const int tid = threadIdx.x;
    if (tid < 256) hist[tid] = 0;
    __syncthreads();

    float4 p[2]; int b[2];
#pragma unroll
    for (int rr = 0; rr < 2; rr++) {
        const int j = tid + rr * 1024;
        const float xx = pos[3 * j], yy = pos[3 * j + 1], zz = pos[3 * j + 2];
        int bb = (int)(xx * 256.0f);
        bb = bb < 0 ? 0 : (bb > 255 ? 255 : bb);
        p[rr] = make_float4(xx, yy, zz, __int_as_float(j));
        b[rr] = bb;
        atomicAdd(&hist[bb], 1);
    }
    __syncthreads();

    if (tid < 256) {
        const int lane = tid & 31, w = tid >> 5;
        const int v = hist[tid];
        int incl = v;
#pragma unroll
        for (int d = 1; d < 32; d <<= 1) {
            const int t = __shfl_up_sync(0xFFFFFFFFu, incl, d);
            if (lane >= d) incl += t;
        }
        if (lane == 31) wsum[w] = incl;
        __syncthreads();
        int woff = 0;
        for (int k = 0; k < w; k++) woff += wsum[k];
        const int excl = woff + incl - v;
        cursor[tid] = excl;
        g_bstart[tid] = excl;
        if (tid == 0) { g_bstart[256] = NPTS; *out_max = 0.0f; }
    } else {
        __syncthreads();
    }
    __syncthreads();

#pragma unroll
    for (int rr = 0; rr < 2; rr++) {
        const int dst = atomicAdd(&cursor[b[rr]], 1);
        g_sorted[dst] = p[rr];
    }
}

__global__ __launch_bounds__(NTHREADS, 7)
void pb_nbr_kernel(const float* __restrict__ pos, float* __restrict__ out) {
    __shared__ unsigned s_mask[ROWS_PER_BLOCK][MWORDS];   // 4 KB
    __shared__ int s_wcnt[ROWS_PER_BLOCK][WARPS_PER_ROW];

    const int tid  = threadIdx.x;
    const int lane = tid & 31;
    const int w    = tid >> 5;
    const int r    = w >> 2;
    const int q    = w & 3;

    unsigned* mz = &s_mask[0][0];
    for (int k = tid; k < ROWS_PER_BLOCK * MWORDS; k += NTHREADS) mz[k] = 0u;
    __syncthreads();

    const int i = blockIdx.x * ROWS_PER_BLOCK + r;
    const float pix = __ldg(&pos[3 * i]);
    const float piy = __ldg(&pos[3 * i + 1]);
    const float piz = __ldg(&pos[3 * i + 2]);

    // Per-dim shift feasibility (margin 1e-4 >> fp32 rounding); -1/+1 mutually exclusive.
    const bool okxm = pix < 0.30001f, okxp = pix > 0.69999f;
    const bool okym = piy < 0.30001f, okyp = piy > 0.69999f;
    const bool okzm = piz < 0.30001f, okzp = piz > 0.69999f;

    const int nx = 1 + okxm + okxp, ny = 1 + okym + okyp, nz = 1 + okzm + okzp;
    const int nA = nx * ny * nz;
    const bool hy = okym || okyp;
    const bool hz = okzm || okzp;
    const float fy = okym ? -1.0f : 1.0f;
    const float fz = okzm ? -1.0f : 1.0f;

    // Ranks within ascending active lists -> slot = (posz*ny+posy)*nx+posx.
    const int posx1 = okxm ? 1 : 0;
    const int posy1 = okym ? 1 : 0;
    const int posz1 = okzm ? 1 : 0;
    const int posyS = okym ? 0 : 1;   // rank of the shifted y (valid iff hy)
    const int poszS = okzm ? 0 : 1;
    const int base00 = (posz1 * ny + posy1) * nx;  // y0 z0
    const int baseY  = (posz1 * ny + posyS) * nx;  // yS z0
    const int baseZ  = (poszS * ny + posy1) * nx;  // y0 zS
    const int baseYZ = (poszS * ny + posyS) * nx;  // yS zS

    // x bucket windows (conservative supersets)
    int blo0 = (int)floorf((pix - 0.3f - EPSB) * 256.0f); if (blo0 < 0) blo0 = 0;
    int bhi0 = (int)floorf((pix + 0.3f + EPSB) * 256.0f); if (bhi0 > 255) bhi0 = 255;
    int blo1 = (int)floorf((pix + 0.7f - EPSB) * 256.0f);
    if (blo1 > 255) blo1 = 255; if (blo1 < 0) blo1 = 0;
    int bhi2 = (int)floorf((pix - 0.7f + EPSB) * 256.0f);
    if (bhi2 > 255) bhi2 = 255; if (bhi2 < 0) bhi2 = 0;

    unsigned* __restrict__ rmask = s_mask[r];

    // ---- Discovery: order-free; hits -> flat slot bitmask via atomicOr ----
#pragma unroll
    for (int s = 0; s < 3; s++) {
        bool sval; float fsx; int posx, kb0, kb1; bool selfchk;
        if (s == 0)      { sval = true; fsx =  0.0f; posx = posx1;  kb0 = blo0; kb1 = bhi0; selfchk = true;  }
        else if (s == 1) { sval = okxm; fsx = -1.0f; posx = 0;      kb0 = blo1; kb1 = 255;  selfchk = false; }
        else             { sval = okxp; fsx =  1.0f; posx = nx - 1; kb0 = 0;    kb1 = bhi2; selfchk = false; }
        if (!sval) continue;
        const int slot00 = base00 + posx;
        const int slotY  = baseY  + posx;
        const int slotZ  = baseZ  + posx;
        const int slotYZ = baseYZ + posx;
        const int k0 = __ldg(&g_bstart[kb0]);
        const int k1 = __ldg(&g_bstart[kb1 + 1]);

        for (int base = k0 + q * 32; base < k1; base += WARPS_PER_ROW * 32) {
            const int k = base + lane;
            const bool val = (k < k1);
            const float4 p = __ldg(&g_sorted[val ? k : k0]);
            const int jorig = __float_as_int(p.w);
            const int jw = jorig >> 5;
            const unsigned jb = 1u << (jorig & 31);
            // Exact reference rounding: ((p_j + s) - p_i), plain mul/add, no FMA.
            const float dx  = __fadd_rn(__fadd_rn(p.x, fsx), -pix);
            const float dx2 = __fmul_rn(dx, dx);
            const float dy0 = __fadd_rn(p.y, -piy);
            const float dz0 = __fadd_rn(p.z, -piz);
            const float dy0s = __fmul_rn(dy0, dy0);
            const float dz0s = __fmul_rn(dz0, dz0);
            {
                const float d2 = __fadd_rn(__fadd_rn(dx2, dy0s), dz0s);
                if (val && d2 <= CUT2 && !(selfchk && jorig == i))
                    atomicOr(&rmask[(slot00 << 6) + jw], jb);
            }
            if (hy) {
                const float dy1 = __fadd_rn(__fadd_rn(p.y, fy), -piy);
                const float dy1s = __fmul_rn(dy1, dy1);
                {
                    const float d2 = __fadd_rn(__fadd_rn(dx2, dy1s), dz0s);
                    if (val && d2 <= CUT2) atomicOr(&rmask[(slotY << 6) + jw], jb);
                }
                if (hz) {
                    const float dz1 = __fadd_rn(__fadd_rn(p.z, fz), -piz);
                    const float dz1s = __fmul_rn(dz1, dz1);
                    const float d2 = __fadd_rn(__fadd_rn(dx2, dy1s), dz1s);
                    if (val && d2 <= CUT2) atomicOr(&rmask[(slotYZ << 6) + jw], jb);
                }
            }
            if (hz) {
                const float dz1 = __fadd_rn(__fadd_rn(p.z, fz), -piz);
                const float dz1s = __fmul_rn(dz1, dz1);
                const float d2 = __fadd_rn(__fadd_rn(dx2, dy0s), dz1s);
                if (val && d2 <= CUT2) atomicOr(&rmask[(slotZ << 6) + jw], jb);
            }
        }
    }
    __syncthreads();

    // ---- Count: contiguous popc sweep over this warp's span ----
    const int myt0 = q * nA * 16;
    const int myt1 = myt0 + nA * 16;
    int cnt = 0;
    for (int t = myt0 + lane; t < myt1; t += 32) cnt += __popc(rmask[t]);
#pragma unroll
    for (int d = 16; d; d >>= 1) cnt += __shfl_xor_sync(0xFFFFFFFFu, cnt, d);
    if (lane == 0) s_wcnt[r][q] = cnt;
    __syncthreads();

    int base = 0, rowTotal = 0;
#pragma unroll
    for (int q2 = 0; q2 < WARPS_PER_ROW; q2++) {
        const int cc = s_wcnt[r][q2];
        if (q2 < q) base += cc;
        rowTotal += cc;
    }

    float* __restrict__ out_neigh = out + (size_t)i * KCAP;
    float* __restrict__ out_cells = out + (size_t)NPTS * KCAP + (size_t)i * KCAP * 3;

    // ---- Emit: slot-ascending (== c-ascending) ordered bit expansion ----
    {
        int off = base;
        int slot = 0;
        for (int zi = 0; zi < 3; zi++) {
            if ((zi == 0 && !okzm) || (zi == 2 && !okzp)) continue;
            for (int yi = 0; yi < 3; yi++) {
                if ((yi == 0 && !okym) || (yi == 2 && !okyp)) continue;
                for (int xi = 0; xi < 3; xi++) {
                    if ((xi == 0 && !okxm) || (xi == 2 && !okxp)) continue;
                    const float fsx = (float)(xi - 1);
                    const float fsy = (float)(yi - 1);
                    const float fsz = (float)(zi - 1);
                    const int tb = slot << 6;
                    const int lo = myt0 > tb ? myt0 : tb;
                    const int hi = myt1 < tb + 64 ? myt1 : tb + 64;
                    for (int tg = lo; tg < hi; tg += 32) {
                        const int t = tg + lane;
                        unsigned word = (t < hi) ? rmask[t] : 0u;
                        const int pc = __popc(word);
                        int ex = pc;
#pragma unroll
                        for (int d = 1; d < 32; d <<= 1) {
                            const int tt = __shfl_up_sync(0xFFFFFFFFu, ex, d);
                            if (lane >= d) ex += tt;
                        }
                        int myoff = off + ex - pc;
                        const int jbase = (t - tb) << 5;
                        while (word) {
                            const int bit = __ffs(word) - 1;
                            word &= word - 1;
                            if (myoff < KCAP) {
                                const int j = jbase + bit;
                                out_neigh[myoff]         = (float)j;
                                out_cells[3 * myoff]     = fsx;
                                out_cells[3 * myoff + 1] = fsy;
                                out_cells[3 * myoff + 2] = fsz;
                            }
                            myoff++;
                        }
                        off += __shfl_sync(0xFFFFFFFFu, ex, 31);
                    }
                    slot++;
                }
            }
        }
    }

    // Tail fill: neighbours=-1, cells=(1,1,1) (jnp.take wraps -1 -> last row)
    const int rowTid = tid & 127;
    const int filled = (rowTotal < KCAP) ? rowTotal : KCAP;
    for (int k = filled + rowTid; k < KCAP; k += 128) {
        out_neigh[k]         = -1.0f;
        out_cells[3 * k]     = 1.0f;
        out_cells[3 * k + 1] = 1.0f;
        out_cells[3 * k + 2] = 1.0f;
    }
    if (q == 0 && lane == 0) {
        atomicMax((int*)(out + MAX_OFFSET), __float_as_int((float)rowTotal));
    }
}

extern "C" void kernel_launch(void* const* d_in, const int* in_sizes, int n_in,
                              void* d_out, int out_size) {
    const float* pos = (const float*)d_in[0];
    float* out = (float*)d_out;
    pb_sort_kernel<<<1, 1024>>>(pos, out + MAX_OFFSET);
    pb_nbr_kernel<<<NPTS / ROWS_PER_BLOCK, NTHREADS>>>(pos, out);
}

// round 12
// speedup vs baseline: 2.8658x; 1.0188x over previous
#include <cuda_runtime.h>

#define NPTS 2048
#define KCAP 256
#define NTHREADS 256
#define ROWS_PER_BLOCK 2
#define WARPS_PER_ROW 4
#define CUT2 0.09f
#define EPSB 1e-3f
#define MWORDS 512    // 8 active-slot cells max * 64 words

#define MAX_OFFSET ((size_t)NPTS * KCAP * 4)

// Scratch (__device__ globals, allocation-free)
__device__ float4 g_sorted[NPTS];   // x-bucket-sorted points; .w = original j (bits)
__device__ int    g_bstart[257];    // bucket start offsets

// Single-block counting sort by x-bucket, 1024 threads (2 pts each).
__global__ __launch_bounds__(1024)
void pb_sort_kernel(const float* __restrict__ pos, float* __restrict__ out_max) {
    __shared__ int hist[256];
    __shared__ int cursor[256];
    __shared__ int wsum[8];
    const int tid = threadIdx.x;
    if (tid < 256) hist[tid] = 0;
    __syncthreads();

    float4 p[2]; int b[2];
#pragma unroll
    for (int rr = 0; rr < 2; rr++) {
        const int j = tid + rr * 1024;
        const float xx = pos[3 * j], yy = pos[3 * j + 1], zz = pos[3 * j + 2];
        int bb = (int)(xx * 256.0f);
        bb = bb < 0 ? 0 : (bb > 255 ? 255 : bb);
        p[rr] = make_float4(xx, yy, zz, __int_as_float(j));
        b[rr] = bb;
        atomicAdd(&hist[bb], 1);
    }
    __syncthreads();

    if (tid < 256) {
        const int lane = tid & 31, w = tid >> 5;
        const int v = hist[tid];
        int incl = v;
#pragma unroll
        for (int d = 1; d < 32; d <<= 1) {
            const int t = __shfl_up_sync(0xFFFFFFFFu, incl, d);
            if (lane >= d) incl += t;
        }
        if (lane == 31) wsum[w] = incl;
        __syncthreads();
        int woff = 0;
        for (int k = 0; k < w; k++) woff += wsum[k];
        const int excl = woff + incl - v;
        cursor[tid] = excl;
        g_bstart[tid] = excl;
        if (tid == 0) { g_bstart[256] = NPTS; *out_max = 0.0f; }
    } else {
        __syncthreads();
    }
    __syncthreads();

#pragma unroll
    for (int rr = 0; rr < 2; rr++) {
        const int dst = atomicAdd(&cursor[b[rr]], 1);
        g_sorted[dst] = p[rr];
    }
}

__global__ __launch_bounds__(NTHREADS, 7)
void pb_nbr_kernel(const float* __restrict__ pos, float* __restrict__ out) {
    __shared__ unsigned s_mask[ROWS_PER_BLOCK][MWORDS];           // 4 KB
    __shared__ unsigned short s_stage[ROWS_PER_BLOCK][KCAP];      // 1 KB
    __shared__ int s_wcnt[ROWS_PER_BLOCK][WARPS_PER_ROW];

    const int tid  = threadIdx.x;
    const int lane = tid & 31;
    const int w    = tid >> 5;
    const int r    = w >> 2;
    const int q    = w & 3;

    unsigned* mz = &s_mask[0][0];
    for (int k = tid; k < ROWS_PER_BLOCK * MWORDS; k += NTHREADS) mz[k] = 0u;
    __syncthreads();

    const int i = blockIdx.x * ROWS_PER_BLOCK + r;
    const float pix = __ldg(&pos[3 * i]);
    const float piy = __ldg(&pos[3 * i + 1]);
    const float piz = __ldg(&pos[3 * i + 2]);

    // Per-dim shift feasibility (margin 1e-4 >> fp32 rounding); -1/+1 mutually exclusive.
    const bool okxm = pix < 0.30001f, okxp = pix > 0.69999f;
    const bool okym = piy < 0.30001f, okyp = piy > 0.69999f;
    const bool okzm = piz < 0.30001f, okzp = piz > 0.69999f;

    const int nx = 1 + okxm + okxp, ny = 1 + okym + okyp, nz = 1 + okzm + okzp;
    const int nA = nx * ny * nz;
    const bool hy = okym || okyp;
    const bool hz = okzm || okzp;
    const float fy = okym ? -1.0f : 1.0f;
    const float fz = okzm ? -1.0f : 1.0f;

    // Ranks within ascending active lists -> slot = (posz*ny+posy)*nx+posx.
    const int posx1 = okxm ? 1 : 0;
    const int posy1 = okym ? 1 : 0;
    const int posz1 = okzm ? 1 : 0;
    const int posyS = okym ? 0 : 1;
    const int poszS = okzm ? 0 : 1;
    const int base00 = (posz1 * ny + posy1) * nx;
    const int baseY  = (posz1 * ny + posyS) * nx;
    const int baseZ  = (poszS * ny + posy1) * nx;
    const int baseYZ = (poszS * ny + posyS) * nx;

    // x bucket windows (conservative supersets)
    int blo0 = (int)floorf((pix - 0.3f - EPSB) * 256.0f); if (blo0 < 0) blo0 = 0;
    int bhi0 = (int)floorf((pix + 0.3f + EPSB) * 256.0f); if (bhi0 > 255) bhi0 = 255;
    int blo1 = (int)floorf((pix + 0.7f - EPSB) * 256.0f);
    if (blo1 > 255) blo1 = 255; if (blo1 < 0) blo1 = 0;
    int bhi2 = (int)floorf((pix - 0.7f + EPSB) * 256.0f);
    if (bhi2 > 255) bhi2 = 255; if (bhi2 < 0) bhi2 = 0;

    unsigned* __restrict__ rmask = s_mask[r];

    // ---- Discovery: order-free; hits -> flat slot bitmask via atomicOr ----
#pragma unroll
    for (int s = 0; s < 3; s++) {
        bool sval; float fsx; int posx, kb0, kb1; bool selfchk;
        if (s == 0)      { sval = true; fsx =  0.0f; posx = posx1;  kb0 = blo0; kb1 = bhi0; selfchk = true;  }
        else if (s == 1) { sval = okxm; fsx = -1.0f; posx = 0;      kb0 = blo1; kb1 = 255;  selfchk = false; }
        else             { sval = okxp; fsx =  1.0f; posx = nx - 1; kb0 = 0;    kb1 = bhi2; selfchk = false; }
        if (!sval) continue;
        const int slot00 = base00 + posx;
        const int slotY  = baseY  + posx;
        const int slotZ  = baseZ  + posx;
        const int slotYZ = baseYZ + posx;
        const int k0 = __ldg(&g_bstart[kb0]);
        const int k1 = __ldg(&g_bstart[kb1 + 1]);

        for (int base = k0 + q * 32; base < k1; base += WARPS_PER_ROW * 32) {
            const int k = base + lane;
            const bool val = (k < k1);
            const float4 p = __ldg(&g_sorted[val ? k : k0]);
            const int jorig = __float_as_int(p.w);
            const int jw = jorig >> 5;
            const unsigned jb = 1u << (jorig & 31);
            // Exact reference rounding: ((p_j + s) - p_i), plain mul/add, no FMA.
            const float dx  = __fadd_rn(__fadd_rn(p.x, fsx), -pix);
            const float dx2 = __fmul_rn(dx, dx);
            const float dy0 = __fadd_rn(p.y, -piy);
            const float dz0 = __fadd_rn(p.z, -piz);
            const float dy0s = __fmul_rn(dy0, dy0);
            const float dz0s = __fmul_rn(dz0, dz0);
            float dy1s = 0.0f, dz1s = 0.0f;
            if (hy) {
                const float dy1 = __fadd_rn(__fadd_rn(p.y, fy), -piy);
                dy1s = __fmul_rn(dy1, dy1);
            }
            if (hz) {
                const float dz1 = __fadd_rn(__fadd_rn(p.z, fz), -piz);
                dz1s = __fmul_rn(dz1, dz1);
            }
            {
                const float d2 = __fadd_rn(__fadd_rn(dx2, dy0s), dz0s);
                if (val && d2 <= CUT2 && !(selfchk && jorig == i))
                    atomicOr(&rmask[(slot00 << 6) + jw], jb);
            }
            if (hy) {
                const float d2 = __fadd_rn(__fadd_rn(dx2, dy1s), dz0s);
                if (val && d2 <= CUT2) atomicOr(&rmask[(slotY << 6) + jw], jb);
                if (hz) {
                    const float d2b = __fadd_rn(__fadd_rn(dx2, dy1s), dz1s);
                    if (val && d2b <= CUT2) atomicOr(&rmask[(slotYZ << 6) + jw], jb);
                }
            }
            if (hz) {
                const float d2 = __fadd_rn(__fadd_rn(dx2, dy0s), dz1s);
                if (val && d2 <= CUT2) atomicOr(&rmask[(slotZ << 6) + jw], jb);
            }
        }
    }
    __syncthreads();

    // ---- Count: contiguous popc sweep over this warp's span ----
    const int myt0 = q * nA * 16;
    const int myt1 = myt0 + nA * 16;
    int cnt = 0;
    for (int t = myt0 + lane; t < myt1; t += 32) cnt += __popc(rmask[t]);
#pragma unroll
    for (int d = 16; d; d >>= 1) cnt += __shfl_xor_sync(0xFFFFFFFFu, cnt, d);
    if (lane == 0) s_wcnt[r][q] = cnt;
    __syncthreads();

    int base = 0, rowTotal = 0;
#pragma unroll
    for (int q2 = 0; q2 < WARPS_PER_ROW; q2++) {
        const int cc = s_wcnt[r][q2];
        if (q2 < q) base += cc;
        rowTotal += cc;
    }

    // ---- Emit phase 1: ordered bit expansion -> 16-bit codes in smem ----
    {
        unsigned short* __restrict__ rstage = s_stage[r];
        int off = base;
        int slot = 0;
        for (int zi = 0; zi < 3; zi++) {
            if ((zi == 0 && !okzm) || (zi == 2 && !okzp)) continue;
            for (int yi = 0; yi < 3; yi++) {
                if ((yi == 0 && !okym) || (yi == 2 && !okyp)) continue;
                for (int xi = 0; xi < 3; xi++) {
                    if ((xi == 0 && !okxm) || (xi == 2 && !okxp)) continue;
                    const int c = zi * 9 + yi * 3 + xi;     // canonical cell id
                    const int ccode = c << 11;
                    const int tb = slot << 6;
                    const int lo = myt0 > tb ? myt0 : tb;
                    const int hi = myt1 < tb + 64 ? myt1 : tb + 64;
                    for (int tg = lo; tg < hi; tg += 32) {
                        const int t = tg + lane;
                        unsigned word = (t < hi) ? rmask[t] : 0u;
                        const int pc = __popc(word);
                        int ex = pc;
#pragma unroll
                        for (int d = 1; d < 32; d <<= 1) {
                            const int tt = __shfl_up_sync(0xFFFFFFFFu, ex, d);
                            if (lane >= d) ex += tt;
                        }
                        int myoff = off + ex - pc;
                        const int jbase = (t - tb) << 5;
                        while (word) {
                            const int bit = __ffs(word) - 1;
                            word &= word - 1;
                            if (myoff < KCAP)
                                rstage[myoff] = (unsigned short)(ccode | (jbase + bit));
                            myoff++;
                        }
                        off += __shfl_sync(0xFFFFFFFFu, ex, 31);
                    }
                    slot++;
                }
            }
        }
    }
    __syncthreads();

    // ---- Emit phase 2: coalesced decode + fused tail fill ----
    float* __restrict__ out_neigh = out + (size_t)i * KCAP;
    float* __restrict__ out_cells = out + (size_t)NPTS * KCAP + (size_t)i * KCAP * 3;
    const unsigned short* __restrict__ rstage = s_stage[r];
    const int rowTid = tid & 127;
    const int filled = (rowTotal < KCAP) ? rowTotal : KCAP;
    for (int e = rowTid; e < KCAP; e += 128) {
        float vn, c0, c1, c2;
        if (e < filled) {
            const int code = rstage[e];
            const int j = code & 2047;
            const int c = code >> 11;
            vn = (float)j;
            c0 = (float)(c % 3 - 1);
            c1 = (float)((c / 3) % 3 - 1);
            c2 = (float)(c / 9 - 1);
        } else {
            vn = -1.0f; c0 = 1.0f; c1 = 1.0f; c2 = 1.0f;
        }
        out_neigh[e]         = vn;
        out_cells[3 * e]     = c0;
        out_cells[3 * e + 1] = c1;
        out_cells[3 * e + 2] = c2;
    }
    if (q == 0 && lane == 0) {
        atomicMax((int*)(out + MAX_OFFSET), __float_as_int((float)rowTotal));
    }
}

extern "C" void kernel_launch(void* const* d_in, const int* in_sizes, int n_in,
                              void* d_out, int out_size) {
    const float* pos = (const float*)d_in[0];
    float* out = (float*)d_out;
    pb_sort_kernel<<<1, 1024>>>(pos, out + MAX_OFFSET);
    pb_nbr_kernel<<<NPTS / ROWS_PER_BLOCK, NTHREADS>>>(pos, out);
}